// round 12
// baseline (speedup 1.0000x reference)
#include <cuda_runtime.h>
#include <cuda_bf16.h>
#include <cstdint>

#define HH      200
#define NWARP   7
#define THREADS 224

// per-warp A staging: tile0 = 32 rows x 128B (SW128-swizzled bf16, k 0..63)
//                     tile1 = 32 rows x 32B  (k 64..79: dist, const-1, pad)
#define T0_BYTES (32 * 128)
#define T1_BYTES (32 * 32)
#define AW_BYTES (T0_BYTES + T1_BYTES)

// B matrix in VECTORIZED mma fragment order: uint4 per (kk, nn-pair, lane).
//   g_B4[(kk*2 + nnp)*32 + lane] = { w(nn=2nnp,r0), w(nn=2nnp,r1),
//                                    w(nn=2nnp+1,r0), w(nn=2nnp+1,r1) }
//   w(nn,r) = pack( B[k0+1][n], B[k0][n] ),  n = 8*nn + (lane>>2),
//             k0 = 16*kk + 8*r + 2*(lane&3)
//   B[k][n]: k<66 -> attn1_W[k][n], k==66 -> attn1_b[n], else 0.
__device__ __align__(16) uint4 g_B4[5 * 2 * 32];

__device__ __forceinline__ uint32_t cvt2bf(float hi, float lo) {
    uint32_t r;
    asm("cvt.rn.bf16x2.f32 %0, %1, %2;" : "=r"(r) : "f"(hi), "f"(lo));
    return r;
}
__device__ __forceinline__ float sigm(float x) {
    return __fdividef(1.f, 1.f + __expf(-x));
}
__device__ __forceinline__ void ldsm_x4(uint32_t addr, uint32_t& r0, uint32_t& r1,
                                        uint32_t& r2, uint32_t& r3) {
    asm volatile("ldmatrix.sync.aligned.m8n8.x4.shared.b16 {%0,%1,%2,%3}, [%4];"
                 : "=r"(r0), "=r"(r1), "=r"(r2), "=r"(r3) : "r"(addr));
}
__device__ __forceinline__ void mma16816(float* d, const uint32_t* a,
                                         uint32_t b0, uint32_t b1) {
    asm volatile(
        "mma.sync.aligned.m16n8k16.row.col.f32.bf16.bf16.f32 "
        "{%0,%1,%2,%3}, {%4,%5,%6,%7}, {%8,%9}, {%0,%1,%2,%3};"
        : "+f"(d[0]), "+f"(d[1]), "+f"(d[2]), "+f"(d[3])
        : "r"(a[0]), "r"(a[1]), "r"(a[2]), "r"(a[3]), "r"(b0), "r"(b1));
}

// ---- prologue: build vectorized fragment-order B (one tiny block) ----------
__global__ void build_Bfrag(const float* __restrict__ attn1_W,
                            const float* __restrict__ attn1_b) {
    int t = threadIdx.x;
    if (t < 5 * 2 * 32) {
        int l   = t & 31;
        int nnp = (t >> 5) & 1;
        int kk  = t >> 6;
        int n0  = 16 * nnp + (l >> 2);
        int n1  = n0 + 8;
        int kb  = 16 * kk + 2 * (l & 3);
        auto bval = [&](int k, int n) -> float {
            if (k < 66)  return attn1_W[k * 32 + n];
            if (k == 66) return attn1_b[n];
            return 0.f;
        };
        uint4 v;
        v.x = cvt2bf(bval(kb + 1, n0), bval(kb,     n0));
        v.y = cvt2bf(bval(kb + 9, n0), bval(kb + 8, n0));
        v.z = cvt2bf(bval(kb + 1, n1), bval(kb,     n1));
        v.w = cvt2bf(bval(kb + 9, n1), bval(kb + 8, n1));
        g_B4[t] = v;
    }
}

// ---------------------------------------------------------------------------
// One block per batch row. 7 warps; warp w owns positions [32w, 32w+32).
// Warps fully independent until the final 56B reduction.
//
// Gather: within each 8-lane row group, lane c loads fp32 chunk c of BOTH
// table rows (full 128B line per LDG.128 per group), multiplies by target
// chunk, converts, stores to SW128-swizzled A; per-lane dot partial goes to
// s_pd[prow*9 + c] (stride 9 coprime 32 -> conflict-free write AND read).
//
// STS swizzle, strength-reduced (XOR-safe):
//   a0(q) = 512q + (q&1 ? baseE^64 : baseE)
//   a1(q) = 512q + (q&1 ? baseE : baseE^64)
//   baseE = 128*rsel + (((c>>1)^rsel)<<4) + 8*(c&1)   [bit6 of baseE == 0]
//
// MMA: D[32, 32] per warp = A[32, 80] x B[80, 32]  (bf16 in, fp32 acc)
// ---------------------------------------------------------------------------
__global__ __launch_bounds__(THREADS, 4)
void nais_kernel(const int*   __restrict__ history,
                 const int*   __restrict__ target,
                 const int*   __restrict__ history_region,
                 const int*   __restrict__ target_region,
                 const float* __restrict__ lat_long,
                 const float* __restrict__ W_hist,
                 const float* __restrict__ W_tgt,
                 const float* __restrict__ W_reg,
                 const float* __restrict__ attn2_W,
                 const float* __restrict__ dist_W,
                 const float* __restrict__ dist_b,
                 float*       __restrict__ out)
{
    __shared__ __align__(16) unsigned char s_A[NWARP * AW_BYTES];
    __shared__ __align__(16) float s_pd[NWARP][32 * 9 + 4];
    __shared__ float2 s_red[NWARP];

    const int b    = blockIdx.x;
    const int tid  = threadIdx.x;
    const int w    = tid >> 5;
    const int lane = tid & 31;
    const int gid  = lane >> 2;
    const int tig  = lane & 3;
    const int base = b * HH;
    const int tgt  = target[b];
    const int treg = target_region[b];
    const int tb   = 32 * w;
    const int c    = lane & 7;     // fp32 16B-chunk within the 128B table row

    unsigned char* myA = s_A + w * AW_BYTES;

    // ---- per-lane position indices (ONE coalesced load each; shfl later)
    const int posl = min(tb + lane, HH - 1);
    const int idxv = history[base + posl];
    const int regv = history_region[base + posl];

    // ---- this lane's target-embedding chunk (uniform per c; L2/L1 hot)
    const float4 th = *(const float4*)(W_tgt + (size_t)tgt * 32 + 4 * c);
    const float4 tr = *(const float4*)(W_reg + (size_t)treg * 32 + 4 * c);

    // ---- tile1 init: row = lane. chunk0 = (dist placeholder, k66=1.0, 0, 0)
    {
        uint4* r = (uint4*)(myA + T0_BYTES + lane * 32);
        r[0] = make_uint4(0u, 0x00003F80u, 0u, 0u);
        r[1] = make_uint4(0u, 0u, 0u, 0u);
    }

    // ---- dist features -> tile1 word0 (same lane, program-ordered after init)
    {
        float2 ll = *(const float2*)(lat_long + (size_t)(base + posl) * 2);
        const float dw00 = dist_W[0] * 100.f, dw01 = dist_W[1] * 100.f;
        const float dw10 = dist_W[2] * 100.f, dw11 = dist_W[3] * 100.f;
        float d0 = sigm(fmaf(ll.x, dw00, fmaf(ll.y, dw10, dist_b[0])));
        float d1 = sigm(fmaf(ll.x, dw01, fmaf(ll.y, dw11, dist_b[1])));
        *(uint32_t*)(myA + T0_BYTES + lane * 32) = cvt2bf(d1, d0);
    }

    // ---- gather + product + cvt + swizzled store + dot-partial store
    {
        const int rsel = lane >> 3;    // which of 4 rows this lane serves per q
        const uint32_t baseE = 128u * rsel + ((((c >> 1) ^ rsel)) << 4)
                             + ((c & 1) << 3);
        unsigned char* d0E = myA + baseE;          // a0 even-q
        unsigned char* d0O = myA + (baseE ^ 64);   // a0 odd-q  (== a1 even-q)
        float* pd = &s_pd[w][c];                   // + 9*prow per q
#pragma unroll
        for (int q = 0; q < 8; q++) {
            int prow = 4 * q + rsel;   // local position 0..31
            int ii = __shfl_sync(0xffffffffu, idxv, prow);
            int rr = __shfl_sync(0xffffffffu, regv, prow);
            float4 eh = *(const float4*)(W_hist + (size_t)ii * 32 + 4 * c);
            float4 er = *(const float4*)(W_reg  + (size_t)rr * 32 + 4 * c);
            float ph0 = eh.x * th.x, ph1 = eh.y * th.y;
            float ph2 = eh.z * th.z, ph3 = eh.w * th.w;
            float pr0 = er.x * tr.x, pr1 = er.y * tr.y;
            float pr2 = er.z * tr.z, pr3 = er.w * tr.w;
            uint2 hv = make_uint2(cvt2bf(ph1, ph0), cvt2bf(ph3, ph2));
            uint2 rv = make_uint2(cvt2bf(pr1, pr0), cvt2bf(pr3, pr2));
            unsigned char* pa0 = ((q & 1) ? d0O : d0E) + 512 * q;
            unsigned char* pa1 = ((q & 1) ? d0E : d0O) + 512 * q;
            *(uint2*)pa0 = hv;
            *(uint2*)pa1 = rv;
            // per-lane dot partial (8 products); reduced in the epilogue
            pd[9 * prow] = ((ph0 + ph1) + (ph2 + ph3))
                         + ((pr0 + pr1) + (pr2 + pr3));
        }
    }
    __syncwarp();   // per-warp only: A tile + s_pd visible to this warp

    // ---- MMA: 2 m-tiles x 4 n-tiles x 5 k-steps; B frags via LDG.128
    float d[2][4][4];
#pragma unroll
    for (int mt = 0; mt < 2; mt++)
#pragma unroll
        for (int nn = 0; nn < 4; nn++)
#pragma unroll
            for (int i = 0; i < 4; i++) d[mt][nn][i] = 0.f;

    const uint32_t aT0 = (uint32_t)__cvta_generic_to_shared(myA);
    const uint32_t aT1 = aT0 + T0_BYTES;

#pragma unroll
    for (int kk = 0; kk < 5; kk++) {
        uint32_t a[2][4];
#pragma unroll
        for (int mt = 0; mt < 2; mt++) {
            int row = 16 * mt + (lane & 15);
            uint32_t addr;
            if (kk < 4) {
                int chunk = 2 * kk + (lane >> 4);
                addr = aT0 + row * 128 + ((chunk ^ (row & 7)) << 4);
            } else {
                addr = aT1 + row * 32 + ((lane >> 4) << 4);
            }
            ldsm_x4(addr, a[mt][0], a[mt][1], a[mt][2], a[mt][3]);
        }
        uint4 B0 = g_B4[(kk * 2    ) * 32 + lane];
        uint4 B1 = g_B4[(kk * 2 + 1) * 32 + lane];
        mma16816(d[0][0], a[0], B0.x, B0.y);
        mma16816(d[1][0], a[1], B0.x, B0.y);
        mma16816(d[0][1], a[0], B0.z, B0.w);
        mma16816(d[1][1], a[1], B0.z, B0.w);
        mma16816(d[0][2], a[0], B1.x, B1.y);
        mma16816(d[1][2], a[1], B1.x, B1.y);
        mma16816(d[0][3], a[0], B1.z, B1.w);
        mma16816(d[1][3], a[1], B1.z, B1.w);
    }

    // ---- epilogue: relu(hid) . w2, dot from s_pd, masked exp, reduce
    float v00 = 0.f, v01 = 0.f, v10 = 0.f, v11 = 0.f;
#pragma unroll
    for (int nn = 0; nn < 4; nn++) {
        float2 w2 = *(const float2*)(attn2_W + 8 * nn + 2 * tig);
        v00 = fmaf(fmaxf(d[0][nn][0], 0.f), w2.x, fmaf(fmaxf(d[0][nn][1], 0.f), w2.y, v00));
        v01 = fmaf(fmaxf(d[0][nn][2], 0.f), w2.x, fmaf(fmaxf(d[0][nn][3], 0.f), w2.y, v01));
        v10 = fmaf(fmaxf(d[1][nn][0], 0.f), w2.x, fmaf(fmaxf(d[1][nn][1], 0.f), w2.y, v10));
        v11 = fmaf(fmaxf(d[1][nn][2], 0.f), w2.x, fmaf(fmaxf(d[1][nn][3], 0.f), w2.y, v11));
    }
#pragma unroll
    for (int off = 1; off <= 2; off <<= 1) {
        v00 += __shfl_xor_sync(0xffffffffu, v00, off);
        v01 += __shfl_xor_sync(0xffffffffu, v01, off);
        v10 += __shfl_xor_sync(0xffffffffu, v10, off);
        v11 += __shfl_xor_sync(0xffffffffu, v11, off);
    }
    float score = (tig == 0) ? v00 : (tig == 1) ? v01 : (tig == 2) ? v10 : v11;

    int posl2 = gid + 8 * tig;                       // local row this lane owns
    const float* pd = &s_pd[w][9 * posl2];           // conflict-free (9 ⊥ 32)
    float dotv = ((pd[0] + pd[1]) + (pd[2] + pd[3]))
               + ((pd[4] + pd[5]) + (pd[6] + pd[7]));
    int idx = __shfl_sync(0xffffffffu, idxv, posl2); // no reload
    bool ok = (idx != tgt) && (tb + posl2 < HH);
    float e  = ok ? __expf(score) : 0.f;
    float se = e;
    float sp = e * dotv;
#pragma unroll
    for (int off = 16; off; off >>= 1) {
        se += __shfl_xor_sync(0xffffffffu, se, off);
        sp += __shfl_xor_sync(0xffffffffu, sp, off);
    }
    if (lane == 0) s_red[w] = make_float2(se, sp);
    __syncthreads();
    if (tid == 0) {
        float SE = 0.f, SP = 0.f;
#pragma unroll
        for (int i = 0; i < NWARP; i++) { SE += s_red[i].x; SP += s_red[i].y; }
        out[b] = sigm(SP * rsqrtf(SE));   // BETA=0.5: pred = SP / sqrt(SE)
    }
}

extern "C" void kernel_launch(void* const* d_in, const int* in_sizes, int n_in,
                              void* d_out, int out_size) {
    const int B = in_sizes[1];   // target is [B]
    build_Bfrag<<<1, 320>>>((const float*)d_in[8], (const float*)d_in[9]);
    nais_kernel<<<B, THREADS>>>(
        (const int*)  d_in[0],   // history [B,H]
        (const int*)  d_in[1],   // target [B]
        (const int*)  d_in[2],   // history_region [B,H]
        (const int*)  d_in[3],   // target_region [B]
        (const float*)d_in[4],   // target_lat_long [B,H,2]
        (const float*)d_in[5],   // W_hist
        (const float*)d_in[6],   // W_tgt
        (const float*)d_in[7],   // W_reg
        (const float*)d_in[10],  // attn2_W [32,1]
        (const float*)d_in[11],  // dist_W [2,2]
        (const float*)d_in[12],  // dist_b [2]
        (float*)d_out);
}

// round 13
// speedup vs baseline: 1.0199x; 1.0199x over previous
#include <cuda_runtime.h>
#include <cuda_bf16.h>
#include <cstdint>

#define HH      200
#define NWARP   7
#define THREADS 224

// per-warp A staging: tile0 = 32 rows x 128B (SW128-swizzled bf16, k 0..63)
//                     tile1 = 32 rows x 32B  (k 64..79: dist, const-1, pad)
#define T0_BYTES (32 * 128)
#define T1_BYTES (32 * 32)
#define AW_BYTES (T0_BYTES + T1_BYTES)

// B matrix in VECTORIZED mma fragment order: uint4 per (kk, nn-pair, lane).
//   g_B4[(kk*2 + nnp)*32 + lane] = { w(nn=2nnp,r0), w(nn=2nnp,r1),
//                                    w(nn=2nnp+1,r0), w(nn=2nnp+1,r1) }
//   w(nn,r) = pack( B[k0+1][n], B[k0][n] ),  n = 8*nn + (lane>>2),
//             k0 = 16*kk + 8*r + 2*(lane&3)
//   B[k][n]: k<66 -> attn1_W[k][n], k==66 -> attn1_b[n], else 0.
__device__ __align__(16) uint4 g_B4[5 * 2 * 32];

__device__ __forceinline__ uint32_t cvt2bf(float hi, float lo) {
    uint32_t r;
    asm("cvt.rn.bf16x2.f32 %0, %1, %2;" : "=r"(r) : "f"(hi), "f"(lo));
    return r;
}
__device__ __forceinline__ float sigm(float x) {
    return __fdividef(1.f, 1.f + __expf(-x));
}
__device__ __forceinline__ void ldsm_x4(uint32_t addr, uint32_t& r0, uint32_t& r1,
                                        uint32_t& r2, uint32_t& r3) {
    asm volatile("ldmatrix.sync.aligned.m8n8.x4.shared.b16 {%0,%1,%2,%3}, [%4];"
                 : "=r"(r0), "=r"(r1), "=r"(r2), "=r"(r3) : "r"(addr));
}
__device__ __forceinline__ void mma16816(float* d, const uint32_t* a,
                                         uint32_t b0, uint32_t b1) {
    asm volatile(
        "mma.sync.aligned.m16n8k16.row.col.f32.bf16.bf16.f32 "
        "{%0,%1,%2,%3}, {%4,%5,%6,%7}, {%8,%9}, {%0,%1,%2,%3};"
        : "+f"(d[0]), "+f"(d[1]), "+f"(d[2]), "+f"(d[3])
        : "r"(a[0]), "r"(a[1]), "r"(a[2]), "r"(a[3]), "r"(b0), "r"(b1));
}

// ---- prologue: build vectorized fragment-order B (one tiny block) ----------
__global__ void build_Bfrag(const float* __restrict__ attn1_W,
                            const float* __restrict__ attn1_b) {
    int t = threadIdx.x;
    if (t < 5 * 2 * 32) {
        int l   = t & 31;
        int nnp = (t >> 5) & 1;
        int kk  = t >> 6;
        int n0  = 16 * nnp + (l >> 2);
        int n1  = n0 + 8;
        int kb  = 16 * kk + 2 * (l & 3);
        auto bval = [&](int k, int n) -> float {
            if (k < 66)  return attn1_W[k * 32 + n];
            if (k == 66) return attn1_b[n];
            return 0.f;
        };
        uint4 v;
        v.x = cvt2bf(bval(kb + 1, n0), bval(kb,     n0));
        v.y = cvt2bf(bval(kb + 9, n0), bval(kb + 8, n0));
        v.z = cvt2bf(bval(kb + 1, n1), bval(kb,     n1));
        v.w = cvt2bf(bval(kb + 9, n1), bval(kb + 8, n1));
        g_B4[t] = v;
    }
}

// ---------------------------------------------------------------------------
// One block per batch row. 7 warps; warp w owns positions [32w, 32w+32).
// Warps fully independent until the final 56B reduction.
//
// Gather (wavefront-optimal): within each 8-lane row group, lane c loads
// fp32 chunk c of BOTH table rows (full 128B line per LDG.128 per group),
// multiplies by target chunk, converts, stores to SW128-swizzled A.
// dot(h,t) via in-loop 3-level 8-lane butterfly -> s_dot (pipelines behind
// the gather LDGs; NOT on the critical path).
//
// STS swizzle, strength-reduced (XOR-safe):
//   a0(q) = 512q + (q&1 ? baseE^64 : baseE)
//   a1(q) = 512q + (q&1 ? baseE : baseE^64)
//   baseE = 128*rsel + (((c>>1)^rsel)<<4) + 8*(c&1)   [bit6 of baseE == 0]
//
// MMA: D[32, 32] per warp = A[32, 80] x B[80, 32]  (bf16 in, fp32 acc)
// ---------------------------------------------------------------------------
__global__ __launch_bounds__(THREADS, 4)
void nais_kernel(const int*   __restrict__ history,
                 const int*   __restrict__ target,
                 const int*   __restrict__ history_region,
                 const int*   __restrict__ target_region,
                 const float* __restrict__ lat_long,
                 const float* __restrict__ W_hist,
                 const float* __restrict__ W_tgt,
                 const float* __restrict__ W_reg,
                 const float* __restrict__ attn2_W,
                 const float* __restrict__ dist_W,
                 const float* __restrict__ dist_b,
                 float*       __restrict__ out)
{
    __shared__ __align__(16) unsigned char s_A[NWARP * AW_BYTES];
    __shared__ float  s_dot[NWARP * 32];
    __shared__ float2 s_red[NWARP];

    const int b    = blockIdx.x;
    const int tid  = threadIdx.x;
    const int w    = tid >> 5;
    const int lane = tid & 31;
    const int gid  = lane >> 2;
    const int tig  = lane & 3;
    const int base = b * HH;
    const int tgt  = target[b];
    const int treg = target_region[b];
    const int tb   = 32 * w;
    const int c    = lane & 7;     // fp32 16B-chunk within the 128B table row

    unsigned char* myA = s_A + w * AW_BYTES;

    // ---- per-lane position indices (ONE coalesced load each; shfl later)
    const int posl = min(tb + lane, HH - 1);
    const int idxv = history[base + posl];
    const int regv = history_region[base + posl];

    // ---- this lane's target-embedding chunk (uniform per c; L2/L1 hot)
    const float4 th = *(const float4*)(W_tgt + (size_t)tgt * 32 + 4 * c);
    const float4 tr = *(const float4*)(W_reg + (size_t)treg * 32 + 4 * c);

    // ---- tile1 init: row = lane. chunk0 = (dist placeholder, k66=1.0, 0, 0)
    {
        uint4* r = (uint4*)(myA + T0_BYTES + lane * 32);
        r[0] = make_uint4(0u, 0x00003F80u, 0u, 0u);
        r[1] = make_uint4(0u, 0u, 0u, 0u);
    }

    // ---- dist features -> tile1 word0 (same lane, program-ordered after init)
    {
        float2 ll = *(const float2*)(lat_long + (size_t)(base + posl) * 2);
        const float dw00 = dist_W[0] * 100.f, dw01 = dist_W[1] * 100.f;
        const float dw10 = dist_W[2] * 100.f, dw11 = dist_W[3] * 100.f;
        float d0 = sigm(fmaf(ll.x, dw00, fmaf(ll.y, dw10, dist_b[0])));
        float d1 = sigm(fmaf(ll.x, dw01, fmaf(ll.y, dw11, dist_b[1])));
        *(uint32_t*)(myA + T0_BYTES + lane * 32) = cvt2bf(d1, d0);
    }

    // ---- gather + product + fp32 dot + cvt + swizzled store
    {
        const int rsel = lane >> 3;    // which of 4 rows this lane serves per q
        const uint32_t baseE = 128u * rsel + ((((c >> 1) ^ rsel)) << 4)
                             + ((c & 1) << 3);
        unsigned char* d0E = myA + baseE;          // a0 even-q
        unsigned char* d0O = myA + (baseE ^ 64);   // a0 odd-q  (== a1 even-q)
#pragma unroll
        for (int q = 0; q < 8; q++) {
            int prow = 4 * q + rsel;   // local position 0..31
            int ii = __shfl_sync(0xffffffffu, idxv, prow);
            int rr = __shfl_sync(0xffffffffu, regv, prow);
            float4 eh = *(const float4*)(W_hist + (size_t)ii * 32 + 4 * c);
            float4 er = *(const float4*)(W_reg  + (size_t)rr * 32 + 4 * c);
            float ph0 = eh.x * th.x, ph1 = eh.y * th.y;
            float ph2 = eh.z * th.z, ph3 = eh.w * th.w;
            float pr0 = er.x * tr.x, pr1 = er.y * tr.y;
            float pr2 = er.z * tr.z, pr3 = er.w * tr.w;
            uint2 hv = make_uint2(cvt2bf(ph1, ph0), cvt2bf(ph3, ph2));
            uint2 rv = make_uint2(cvt2bf(pr1, pr0), cvt2bf(pr3, pr2));
            unsigned char* pa0 = ((q & 1) ? d0O : d0E) + 512 * q;
            unsigned char* pa1 = ((q & 1) ? d0E : d0O) + 512 * q;
            *(uint2*)pa0 = hv;
            *(uint2*)pa1 = rv;
            // fp32 dot over the 8 lanes sharing this row (pipelined butterfly)
            float part = ((ph0 + ph1) + (ph2 + ph3)) + ((pr0 + pr1) + (pr2 + pr3));
            part += __shfl_xor_sync(0xffffffffu, part, 1);
            part += __shfl_xor_sync(0xffffffffu, part, 2);
            part += __shfl_xor_sync(0xffffffffu, part, 4);
            if (c == 0) s_dot[w * 32 + prow] = part;
        }
    }
    __syncwarp();   // per-warp only: A tile + s_dot visible to this warp

    // ---- MMA: 2 m-tiles x 4 n-tiles x 5 k-steps; B frags via LDG.128
    float d[2][4][4];
#pragma unroll
    for (int mt = 0; mt < 2; mt++)
#pragma unroll
        for (int nn = 0; nn < 4; nn++)
#pragma unroll
            for (int i = 0; i < 4; i++) d[mt][nn][i] = 0.f;

    const uint32_t aT0 = (uint32_t)__cvta_generic_to_shared(myA);
    const uint32_t aT1 = aT0 + T0_BYTES;

#pragma unroll
    for (int kk = 0; kk < 5; kk++) {
        uint32_t a[2][4];
#pragma unroll
        for (int mt = 0; mt < 2; mt++) {
            int row = 16 * mt + (lane & 15);
            uint32_t addr;
            if (kk < 4) {
                int chunk = 2 * kk + (lane >> 4);
                addr = aT0 + row * 128 + ((chunk ^ (row & 7)) << 4);
            } else {
                addr = aT1 + row * 32 + ((lane >> 4) << 4);
            }
            ldsm_x4(addr, a[mt][0], a[mt][1], a[mt][2], a[mt][3]);
        }
        uint4 B0 = g_B4[(kk * 2    ) * 32 + lane];
        uint4 B1 = g_B4[(kk * 2 + 1) * 32 + lane];
        mma16816(d[0][0], a[0], B0.x, B0.y);
        mma16816(d[1][0], a[1], B0.x, B0.y);
        mma16816(d[0][1], a[0], B0.z, B0.w);
        mma16816(d[1][1], a[1], B0.z, B0.w);
        mma16816(d[0][2], a[0], B1.x, B1.y);
        mma16816(d[1][2], a[1], B1.x, B1.y);
        mma16816(d[0][3], a[0], B1.z, B1.w);
        mma16816(d[1][3], a[1], B1.z, B1.w);
    }

    // ---- epilogue: relu(hid) . w2, masked exp, reduce
    float v00 = 0.f, v01 = 0.f, v10 = 0.f, v11 = 0.f;
#pragma unroll
    for (int nn = 0; nn < 4; nn++) {
        float2 w2 = *(const float2*)(attn2_W + 8 * nn + 2 * tig);
        v00 = fmaf(fmaxf(d[0][nn][0], 0.f), w2.x, fmaf(fmaxf(d[0][nn][1], 0.f), w2.y, v00));
        v01 = fmaf(fmaxf(d[0][nn][2], 0.f), w2.x, fmaf(fmaxf(d[0][nn][3], 0.f), w2.y, v01));
        v10 = fmaf(fmaxf(d[1][nn][0], 0.f), w2.x, fmaf(fmaxf(d[1][nn][1], 0.f), w2.y, v10));
        v11 = fmaf(fmaxf(d[1][nn][2], 0.f), w2.x, fmaf(fmaxf(d[1][nn][3], 0.f), w2.y, v11));
    }
#pragma unroll
    for (int off = 1; off <= 2; off <<= 1) {
        v00 += __shfl_xor_sync(0xffffffffu, v00, off);
        v01 += __shfl_xor_sync(0xffffffffu, v01, off);
        v10 += __shfl_xor_sync(0xffffffffu, v10, off);
        v11 += __shfl_xor_sync(0xffffffffu, v11, off);
    }
    float score = (tig == 0) ? v00 : (tig == 1) ? v01 : (tig == 2) ? v10 : v11;

    int posl2 = gid + 8 * tig;                       // local row this lane owns
    float dotv = s_dot[w * 32 + posl2];              // fp32 dot (conflict-free)
    int idx = __shfl_sync(0xffffffffu, idxv, posl2); // no reload
    bool ok = (idx != tgt) && (tb + posl2 < HH);
    float e  = ok ? __expf(score) : 0.f;
    float se = e;
    float sp = e * dotv;
#pragma unroll
    for (int off = 16; off; off >>= 1) {
        se += __shfl_xor_sync(0xffffffffu, se, off);
        sp += __shfl_xor_sync(0xffffffffu, sp, off);
    }
    if (lane == 0) s_red[w] = make_float2(se, sp);
    __syncthreads();
    if (tid == 0) {
        float SE = 0.f, SP = 0.f;
#pragma unroll
        for (int i = 0; i < NWARP; i++) { SE += s_red[i].x; SP += s_red[i].y; }
        out[b] = sigm(SP * rsqrtf(SE));   // BETA=0.5: pred = SP / sqrt(SE)
    }
}

extern "C" void kernel_launch(void* const* d_in, const int* in_sizes, int n_in,
                              void* d_out, int out_size) {
    const int B = in_sizes[1];   // target is [B]
    build_Bfrag<<<1, 320>>>((const float*)d_in[8], (const float*)d_in[9]);
    nais_kernel<<<B, THREADS>>>(
        (const int*)  d_in[0],   // history [B,H]
        (const int*)  d_in[1],   // target [B]
        (const int*)  d_in[2],   // history_region [B,H]
        (const int*)  d_in[3],   // target_region [B]
        (const float*)d_in[4],   // target_lat_long [B,H,2]
        (const float*)d_in[5],   // W_hist
        (const float*)d_in[6],   // W_tgt
        (const float*)d_in[7],   // W_reg
        (const float*)d_in[10],  // attn2_W [32,1]
        (const float*)d_in[11],  // dist_W [2,2]
        (const float*)d_in[12],  // dist_b [2]
        (float*)d_out);
}

// round 14
// speedup vs baseline: 1.0684x; 1.0476x over previous
#include <cuda_runtime.h>
#include <cuda_bf16.h>
#include <cstdint>

#define HH      200
#define NWARP   7
#define THREADS 224

// per-warp A staging: tile0 = 32 rows x 128B (SW128-swizzled bf16, k' 0..63)
//                     tile1 = 32 rows x 32B  (k' 64..79: dist, const-1, pad)
// A k-PERMUTATION: chunk c of a row holds products
//   [ h(4c) h(4c+1) h(4c+2) h(4c+3) r(4c) r(4c+1) r(4c+2) r(4c+3) ]
// i.e. orig k = pi(kf):  c = kf>>3, j = kf&7,  pi = j<4 ? 4c+j : 28+4c+j
#define T0_BYTES (32 * 128)
#define T1_BYTES (32 * 32)
#define AW_BYTES (T0_BYTES + T1_BYTES)

// B matrix in VECTORIZED mma fragment order (rows follow the SAME pi):
//   g_B4[(kk*2 + nnp)*32 + lane] = { w(nn=2nnp,r0), w(nn=2nnp,r1),
//                                    w(nn=2nnp+1,r0), w(nn=2nnp+1,r1) }
//   w(nn,r) = pack( B[pi(kf0+1)][n], B[pi(kf0)][n] ), n = 8*nn + (lane>>2),
//             kf0 = 16*kk + 8*r + 2*(lane&3)
//   B[k][n]: k<66 -> attn1_W[k][n], k==66 -> attn1_b[n], else 0.
__device__ __align__(16) uint4 g_B4[5 * 2 * 32];

__device__ __forceinline__ uint32_t cvt2bf(float hi, float lo) {
    uint32_t r;
    asm("cvt.rn.bf16x2.f32 %0, %1, %2;" : "=r"(r) : "f"(hi), "f"(lo));
    return r;
}
__device__ __forceinline__ float sigm(float x) {
    return __fdividef(1.f, 1.f + __expf(-x));
}
__device__ __forceinline__ void ldsm_x4(uint32_t addr, uint32_t& r0, uint32_t& r1,
                                        uint32_t& r2, uint32_t& r3) {
    asm volatile("ldmatrix.sync.aligned.m8n8.x4.shared.b16 {%0,%1,%2,%3}, [%4];"
                 : "=r"(r0), "=r"(r1), "=r"(r2), "=r"(r3) : "r"(addr));
}
__device__ __forceinline__ void mma16816(float* d, const uint32_t* a,
                                         uint32_t b0, uint32_t b1) {
    asm volatile(
        "mma.sync.aligned.m16n8k16.row.col.f32.bf16.bf16.f32 "
        "{%0,%1,%2,%3}, {%4,%5,%6,%7}, {%8,%9}, {%0,%1,%2,%3};"
        : "+f"(d[0]), "+f"(d[1]), "+f"(d[2]), "+f"(d[3])
        : "r"(a[0]), "r"(a[1]), "r"(a[2]), "r"(a[3]), "r"(b0), "r"(b1));
}

// ---- prologue: build permuted, vectorized fragment-order B -----------------
__global__ void build_Bfrag(const float* __restrict__ attn1_W,
                            const float* __restrict__ attn1_b) {
    int t = threadIdx.x;
    if (t < 5 * 2 * 32) {
        int l   = t & 31;
        int nnp = (t >> 5) & 1;
        int kk  = t >> 6;
        int n0  = 16 * nnp + (l >> 2);
        int n1  = n0 + 8;
        auto pi = [](int kf) -> int {              // A column permutation
            if (kf >= 64) return kf;               // tile1 unpermuted
            int c = kf >> 3, j = kf & 7;
            return (j < 4) ? (4 * c + j) : (28 + 4 * c + j);
        };
        auto bval = [&](int kf, int n) -> float {  // weight for A column kf
            int k = pi(kf);
            if (k < 66)  return attn1_W[k * 32 + n];
            if (k == 66) return attn1_b[n];
            return 0.f;
        };
        int kb = 16 * kk + 2 * (l & 3);
        uint4 v;
        v.x = cvt2bf(bval(kb + 1, n0), bval(kb,     n0));
        v.y = cvt2bf(bval(kb + 9, n0), bval(kb + 8, n0));
        v.z = cvt2bf(bval(kb + 1, n1), bval(kb,     n1));
        v.w = cvt2bf(bval(kb + 9, n1), bval(kb + 8, n1));
        g_B4[t] = v;
    }
}

// ---------------------------------------------------------------------------
// One block per batch row. 7 warps; warp w owns positions [32w, 32w+32).
// Warps fully independent until the final 56B reduction.
//
// Gather (wavefront-optimal): within each 8-lane row group, lane c loads
// fp32 chunk c of BOTH table rows (full 128B line per LDG.128 per group),
// multiplies by target chunk, converts, and writes ONE STS.128 to swizzled
// chunk c of its row (k-permuted layout). Indices travel as ONE packed word
// (idx<<10 | reg) via a single shfl per q. dot(h,t) via in-loop butterfly.
//
// MMA: D[32, 32] per warp = A[32, 80] x B[80, 32]  (bf16 in, fp32 acc)
// ---------------------------------------------------------------------------
__global__ __launch_bounds__(THREADS, 4)
void nais_kernel(const int*   __restrict__ history,
                 const int*   __restrict__ target,
                 const int*   __restrict__ history_region,
                 const int*   __restrict__ target_region,
                 const float* __restrict__ lat_long,
                 const float* __restrict__ W_hist,
                 const float* __restrict__ W_tgt,
                 const float* __restrict__ W_reg,
                 const float* __restrict__ attn2_W,
                 const float* __restrict__ dist_W,
                 const float* __restrict__ dist_b,
                 float*       __restrict__ out)
{
    __shared__ __align__(16) unsigned char s_A[NWARP * AW_BYTES];
    __shared__ float  s_dot[NWARP * 32];
    __shared__ float2 s_red[NWARP];

    const int b    = blockIdx.x;
    const int tid  = threadIdx.x;
    const int w    = tid >> 5;
    const int lane = tid & 31;
    const int gid  = lane >> 2;
    const int tig  = lane & 3;
    const int base = b * HH;
    const int tgt  = target[b];
    const int treg = target_region[b];
    const int tb   = 32 * w;
    const int c    = lane & 7;     // fp32 16B-chunk within the 128B table row

    unsigned char* myA = s_A + w * AW_BYTES;

    // ---- per-lane packed indices (idx<0x20000, reg<0x400 -> 27 bits)
    const int posl = min(tb + lane, HH - 1);
    const int pk   = (history[base + posl] << 10) | history_region[base + posl];

    // ---- this lane's target-embedding chunk (uniform per c; L2/L1 hot)
    const float4 th = *(const float4*)(W_tgt + (size_t)tgt * 32 + 4 * c);
    const float4 tr = *(const float4*)(W_reg + (size_t)treg * 32 + 4 * c);

    // ---- tile1 init: row = lane. chunk0 = (dist placeholder, k66=1.0, 0, 0)
    {
        uint4* r = (uint4*)(myA + T0_BYTES + lane * 32);
        r[0] = make_uint4(0u, 0x00003F80u, 0u, 0u);
        r[1] = make_uint4(0u, 0u, 0u, 0u);
    }

    // ---- dist features -> tile1 word0 (same lane, program-ordered after init)
    {
        float2 ll = *(const float2*)(lat_long + (size_t)(base + posl) * 2);
        const float dw00 = dist_W[0] * 100.f, dw01 = dist_W[1] * 100.f;
        const float dw10 = dist_W[2] * 100.f, dw11 = dist_W[3] * 100.f;
        float d0 = sigm(fmaf(ll.x, dw00, fmaf(ll.y, dw10, dist_b[0])));
        float d1 = sigm(fmaf(ll.x, dw01, fmaf(ll.y, dw11, dist_b[1])));
        *(uint32_t*)(myA + T0_BYTES + lane * 32) = cvt2bf(d1, d0);
    }

    // ---- gather + product + fp32 dot + cvt + ONE swizzled STS.128 per q
    {
        const int rsel = lane >> 3;    // which of 4 rows this lane serves per q
        const uint32_t baseE = 128u * rsel + ((c ^ rsel) << 4);
        unsigned char* dE = myA + baseE;           // even q
        unsigned char* dO = myA + (baseE ^ 64);    // odd q
#pragma unroll
        for (int q = 0; q < 8; q++) {
            int prow = 4 * q + rsel;   // local position 0..31
            int pq = __shfl_sync(0xffffffffu, pk, prow);
            int ii = pq >> 10;
            int rr = pq & 1023;
            float4 eh = *(const float4*)(W_hist + (size_t)ii * 32 + 4 * c);
            float4 er = *(const float4*)(W_reg  + (size_t)rr * 32 + 4 * c);
            float ph0 = eh.x * th.x, ph1 = eh.y * th.y;
            float ph2 = eh.z * th.z, ph3 = eh.w * th.w;
            float pr0 = er.x * tr.x, pr1 = er.y * tr.y;
            float pr2 = er.z * tr.z, pr3 = er.w * tr.w;
            uint4 v = make_uint4(cvt2bf(ph1, ph0), cvt2bf(ph3, ph2),
                                 cvt2bf(pr1, pr0), cvt2bf(pr3, pr2));
            *(uint4*)(((q & 1) ? dO : dE) + 512 * q) = v;
            // fp32 dot over the 8 lanes sharing this row (pipelined butterfly)
            float part = ((ph0 + ph1) + (ph2 + ph3)) + ((pr0 + pr1) + (pr2 + pr3));
            part += __shfl_xor_sync(0xffffffffu, part, 1);
            part += __shfl_xor_sync(0xffffffffu, part, 2);
            part += __shfl_xor_sync(0xffffffffu, part, 4);
            if (c == 0) s_dot[w * 32 + prow] = part;
        }
    }
    __syncwarp();   // per-warp only: A tile + s_dot visible to this warp

    // ---- MMA: 2 m-tiles x 4 n-tiles x 5 k-steps; B frags via LDG.128
    float d[2][4][4];
#pragma unroll
    for (int mt = 0; mt < 2; mt++)
#pragma unroll
        for (int nn = 0; nn < 4; nn++)
#pragma unroll
            for (int i = 0; i < 4; i++) d[mt][nn][i] = 0.f;

    const uint32_t aT0 = (uint32_t)__cvta_generic_to_shared(myA);
    const uint32_t aT1 = aT0 + T0_BYTES;

#pragma unroll
    for (int kk = 0; kk < 5; kk++) {
        uint32_t a[2][4];
#pragma unroll
        for (int mt = 0; mt < 2; mt++) {
            int row = 16 * mt + (lane & 15);
            uint32_t addr;
            if (kk < 4) {
                int chunk = 2 * kk + (lane >> 4);
                addr = aT0 + row * 128 + ((chunk ^ (row & 7)) << 4);
            } else {
                addr = aT1 + row * 32 + ((lane >> 4) << 4);
            }
            ldsm_x4(addr, a[mt][0], a[mt][1], a[mt][2], a[mt][3]);
        }
        uint4 B0 = g_B4[(kk * 2    ) * 32 + lane];
        uint4 B1 = g_B4[(kk * 2 + 1) * 32 + lane];
        mma16816(d[0][0], a[0], B0.x, B0.y);
        mma16816(d[1][0], a[1], B0.x, B0.y);
        mma16816(d[0][1], a[0], B0.z, B0.w);
        mma16816(d[1][1], a[1], B0.z, B0.w);
        mma16816(d[0][2], a[0], B1.x, B1.y);
        mma16816(d[1][2], a[1], B1.x, B1.y);
        mma16816(d[0][3], a[0], B1.z, B1.w);
        mma16816(d[1][3], a[1], B1.z, B1.w);
    }

    // ---- epilogue: relu(hid) . w2, masked exp, reduce
    float v00 = 0.f, v01 = 0.f, v10 = 0.f, v11 = 0.f;
#pragma unroll
    for (int nn = 0; nn < 4; nn++) {
        float2 w2 = *(const float2*)(attn2_W + 8 * nn + 2 * tig);
        v00 = fmaf(fmaxf(d[0][nn][0], 0.f), w2.x, fmaf(fmaxf(d[0][nn][1], 0.f), w2.y, v00));
        v01 = fmaf(fmaxf(d[0][nn][2], 0.f), w2.x, fmaf(fmaxf(d[0][nn][3], 0.f), w2.y, v01));
        v10 = fmaf(fmaxf(d[1][nn][0], 0.f), w2.x, fmaf(fmaxf(d[1][nn][1], 0.f), w2.y, v10));
        v11 = fmaf(fmaxf(d[1][nn][2], 0.f), w2.x, fmaf(fmaxf(d[1][nn][3], 0.f), w2.y, v11));
    }
#pragma unroll
    for (int off = 1; off <= 2; off <<= 1) {
        v00 += __shfl_xor_sync(0xffffffffu, v00, off);
        v01 += __shfl_xor_sync(0xffffffffu, v01, off);
        v10 += __shfl_xor_sync(0xffffffffu, v10, off);
        v11 += __shfl_xor_sync(0xffffffffu, v11, off);
    }
    float score = (tig == 0) ? v00 : (tig == 1) ? v01 : (tig == 2) ? v10 : v11;

    int posl2 = gid + 8 * tig;                       // local row this lane owns
    float dotv = s_dot[w * 32 + posl2];              // fp32 dot (conflict-free)
    int idx = __shfl_sync(0xffffffffu, pk, posl2) >> 10;   // no reload
    bool ok = (idx != tgt) && (tb + posl2 < HH);
    float e  = ok ? __expf(score) : 0.f;
    float se = e;
    float sp = e * dotv;
#pragma unroll
    for (int off = 16; off; off >>= 1) {
        se += __shfl_xor_sync(0xffffffffu, se, off);
        sp += __shfl_xor_sync(0xffffffffu, sp, off);
    }
    if (lane == 0) s_red[w] = make_float2(se, sp);
    __syncthreads();
    if (tid == 0) {
        float SE = 0.f, SP = 0.f;
#pragma unroll
        for (int i = 0; i < NWARP; i++) { SE += s_red[i].x; SP += s_red[i].y; }
        out[b] = sigm(SP * rsqrtf(SE));   // BETA=0.5: pred = SP / sqrt(SE)
    }
}

extern "C" void kernel_launch(void* const* d_in, const int* in_sizes, int n_in,
                              void* d_out, int out_size) {
    const int B = in_sizes[1];   // target is [B]
    build_Bfrag<<<1, 320>>>((const float*)d_in[8], (const float*)d_in[9]);
    nais_kernel<<<B, THREADS>>>(
        (const int*)  d_in[0],   // history [B,H]
        (const int*)  d_in[1],   // target [B]
        (const int*)  d_in[2],   // history_region [B,H]
        (const int*)  d_in[3],   // target_region [B]
        (const float*)d_in[4],   // target_lat_long [B,H,2]
        (const float*)d_in[5],   // W_hist
        (const float*)d_in[6],   // W_tgt
        (const float*)d_in[7],   // W_reg
        (const float*)d_in[10],  // attn2_W [32,1]
        (const float*)d_in[11],  // dist_W [2,2]
        (const float*)d_in[12],  // dist_b [2]
        (float*)d_out);
}